// round 17
// baseline (speedup 1.0000x reference)
#include <cuda_runtime.h>
#include <math.h>
#include <stdint.h>

#define H 1024
#define V 50257
#define L 512
#define GRID 148
#define TPB 1024
#define NW 32                  // warps per block
#define ROWS_PB 340            // ceil(V / GRID)
#define STICKY_ROWS 136        // per-block out_W rows pinned L2-sticky (~78.6 MB total)
#define NEG_SENT (-1e30f)      // finite LSE identity

// ---------------- scratch (device globals; no allocations allowed) ----------
__device__ float g_qpart[2048];          // attn score quarter-partials
__device__ float g_attn_partial[8][H];
__device__ float g_gru_in[H];
__device__ float g_gates[6 * H];         // [0,3H)=gx, [3H,6H)=gh
__device__ float g_pm[GRID], g_ps[GRID];
__device__ unsigned g_bars[8];

__global__ void k_reset() {
    if (threadIdx.x < 8) g_bars[threadIdx.x] = 0u;
}

// ---- cache-policy based hinted loads (createpolicy + L2::cache_hint form) --
__device__ __forceinline__ uint64_t mkpol_last() {
    uint64_t p;
    asm("createpolicy.fractional.L2::evict_last.b64 %0, 1.0;" : "=l"(p));
    return p;
}
__device__ __forceinline__ uint64_t mkpol_first() {
    uint64_t p;
    asm("createpolicy.fractional.L2::evict_first.b64 %0, 1.0;" : "=l"(p));
    return p;
}
__device__ __forceinline__ float4 ldg4_pol(const float4* p, uint64_t pol) {
    float4 v;
    asm volatile("ld.global.nc.L2::cache_hint.v4.f32 {%0,%1,%2,%3},[%4],%5;"
                 : "=f"(v.x), "=f"(v.y), "=f"(v.z), "=f"(v.w) : "l"(p), "l"(pol));
    return v;
}
__device__ __forceinline__ float ldg1_pol(const float* p, uint64_t pol) {
    float v;
    asm volatile("ld.global.nc.L2::cache_hint.f32 %0,[%1],%2;"
                 : "=f"(v) : "l"(p), "l"(pol));
    return v;
}
__device__ __forceinline__ float ldg1(const float* p) {
    float v;
    asm volatile("ld.global.nc.f32 %0,[%1];" : "=f"(v) : "l"(p));
    return v;
}
__device__ __forceinline__ float wsum(float v) {
#pragma unroll
    for (int o = 16; o; o >>= 1) v += __shfl_down_sync(0xffffffffu, v, o);
    return v;
}

// grid barrier: 148 CTAs, 1/SM, all resident in wave 1 -> spin safe.
__device__ __forceinline__ void gbar(int ph) {
    __syncthreads();
    if (threadIdx.x == 0) {
        __threadfence();
        unsigned arrived = atomicAdd(&g_bars[ph], 1u) + 1u;
        if (arrived < GRID) {
            volatile unsigned* p = &g_bars[ph];
            while (*p < GRID) { __nanosleep(64); }
        }
        __threadfence();
    }
    __syncthreads();
}

__global__ void __launch_bounds__(TPB, 1)
k_fused(const int* __restrict__ x,
        const float* __restrict__ enc,
        const float* __restrict__ hidden,
        const float* __restrict__ emb,
        const float* __restrict__ attn_W,
        const float* __restrict__ attn_b,
        const float* __restrict__ comb_W,
        const float* __restrict__ comb_b,
        const float* __restrict__ W_ih,
        const float* __restrict__ W_hh,
        const float* __restrict__ b_ih,
        const float* __restrict__ b_hh,
        const float* __restrict__ out_W,
        const float* __restrict__ out_b,
        float* __restrict__ out) {
    __shared__ float s_emb[H];
    __shared__ float s_h0[H];
    __shared__ float s_vec[H];
    __shared__ float s_attnw[L];
    __shared__ float red[1024], red2[1024];
    __shared__ float s_outb[ROWS_PB];
    __shared__ float s_logits[ROWS_PB];

    const int t = threadIdx.x, b = blockIdx.x;
    const int wid = t >> 5, lane = t & 31;
    const uint64_t POL_L = mkpol_last();
    const uint64_t POL_F = mkpol_first();

    const int r0 = b * ROWS_PB;
    const int r1 = (r0 + ROWS_PB < V) ? (r0 + ROWS_PB) : V;
    const int nrows = r1 - r0;

    // preload emb row + hidden + out_b slice into shared
    {
        const float* er = emb + (size_t)x[0] * H;
        s_emb[t] = ldg1_pol(er + t, POL_L);
        s_h0[t] = ldg1(hidden + t);
        if (t < nrows) s_outb[t] = ldg1(out_b + r0 + t);
        __syncthreads();
    }

    // ---- Phase A: attn-score quarter partials (2048 jobs)
    //      + W_hh gate GEMV (3072 jobs) — depend only on inputs --------------
    for (int job = b * NW + wid; job < 5120; job += GRID * NW) {
        if (job < 2048) {
            const int row = job >> 2, q = job & 3;
            const float* vp = (q < 2) ? (s_emb + q * 512) : (s_h0 + (q - 2) * 512);
            const float4* Wr = (const float4*)(attn_W + (size_t)row * (2 * H) + q * 512);
            const float4* sv = (const float4*)vp;
            float4 w[4];
#pragma unroll
            for (int i = 0; i < 4; i++) w[i] = ldg4_pol(Wr + lane + i * 32, POL_L);
            float acc = 0.f;
#pragma unroll
            for (int i = 0; i < 4; i++) {
                float4 v = sv[lane + i * 32];
                acc += w[i].x * v.x + w[i].y * v.y + w[i].z * v.z + w[i].w * v.w;
            }
            acc = wsum(acc);
            if (lane == 0) g_qpart[job] = acc;
        } else {
            const int r = job - 2048;
            const float4* Wr = (const float4*)(W_hh + (size_t)r * H);
            const float4* sv = (const float4*)s_h0;
            float4 w[8];
#pragma unroll
            for (int i = 0; i < 8; i++) w[i] = ldg4_pol(Wr + lane + i * 32, POL_L);
            float acc = 0.f;
#pragma unroll
            for (int i = 0; i < 8; i++) {
                float4 v = sv[lane + i * 32];
                acc += w[i].x * v.x + w[i].y * v.y + w[i].z * v.z + w[i].w * v.w;
            }
            acc = wsum(acc);
            if (lane == 0) g_gates[3 * H + r] = acc + ldg1(b_hh + r);
        }
    }
    gbar(0);

    // ---- Phase B: blocks 0..63: redundant softmax (L=512), then attn apply -
    if (b < 64) {
        float sc = NEG_SENT;
        if (t < L)
            sc = g_qpart[4 * t] + g_qpart[4 * t + 1] + g_qpart[4 * t + 2]
               + g_qpart[4 * t + 3] + ldg1(attn_b + t);
        red[t] = sc;
        __syncthreads();
        for (int o = 512; o; o >>= 1) {
            if (t < o) red[t] = fmaxf(red[t], red[t + o]);
            __syncthreads();
        }
        const float m = red[0];
        __syncthreads();
        const float e = (t < L) ? expf(sc - m) : 0.f;
        red[t] = e;
        __syncthreads();
        for (int o = 512; o; o >>= 1) {
            if (t < o) red[t] += red[t + o];
            __syncthreads();
        }
        if (t < L) {
            const float aw = e / red[0];
            s_attnw[t] = aw;
            if (b == 0) out[V + t] = aw;
        }
        __syncthreads();

        const int lc = b >> 3, jc = b & 7;
        const int j = jc * 128 + (t & 127);
        const int sub = t >> 7;                  // 0..7, 8 L-rows each
        const int l0 = lc * 64 + sub * 8;
        float ev[8];
#pragma unroll
        for (int u = 0; u < 8; u++) ev[u] = ldg1_pol(enc + (size_t)(l0 + u) * H + j, POL_L);
        float acc = 0.f;
#pragma unroll
        for (int u = 0; u < 8; u++) acc += s_attnw[l0 + u] * ev[u];
        red[t] = acc;
        __syncthreads();
        if (t < 512) red[t] += red[t + 512];
        __syncthreads();
        if (t < 256) red[t] += red[t + 256];
        __syncthreads();
        if (t < 128)
            g_attn_partial[lc][jc * 128 + t] = red[t] + red[t + 128];
    }
    gbar(1);

    // ---- Phase C: blocks 0..63: combine + relu (16 rows/block, 2 warps/row)
    if (b < 64) {
        {
            float a = 0.f;
#pragma unroll
            for (int c = 0; c < 8; c++) a += g_attn_partial[c][t];
            s_vec[t] = a;
        }
        __syncthreads();
        const int row = b * 16 + (wid >> 1), half = wid & 1;
        const float* vp = half ? s_vec : s_emb;
        const float4* Wr = (const float4*)(comb_W + (size_t)row * (2 * H) + half * H);
        const float4* sv = (const float4*)vp;
        float4 w[8];
#pragma unroll
        for (int i = 0; i < 8; i++) w[i] = ldg4_pol(Wr + lane + i * 32, POL_L);
        float acc = 0.f;
#pragma unroll
        for (int i = 0; i < 8; i++) {
            float4 v = sv[lane + i * 32];
            acc += w[i].x * v.x + w[i].y * v.y + w[i].z * v.z + w[i].w * v.w;
        }
        acc = wsum(acc);
        if (lane == 0) red[wid] = acc;
        __syncthreads();
        if (t < 16) {
            const int r = b * 16 + t;
            g_gru_in[r] = fmaxf(red[2 * t] + red[2 * t + 1] + ldg1(comb_b + r), 0.f);
        }
    }
    gbar(2);

    // ---- Phase D: W_ih gate GEMV (3072 warp-jobs) --------------------------
    s_vec[t] = g_gru_in[t];
    __syncthreads();
    for (int job = b * NW + wid; job < 3 * H; job += GRID * NW) {
        const float4* Wr = (const float4*)(W_ih + (size_t)job * H);
        const float4* sv = (const float4*)s_vec;
        float4 w[8];
#pragma unroll
        for (int i = 0; i < 8; i++) w[i] = ldg4_pol(Wr + lane + i * 32, POL_L);
        float acc = 0.f;
#pragma unroll
        for (int i = 0; i < 8; i++) {
            float4 v = sv[lane + i * 32];
            acc += w[i].x * v.x + w[i].y * v.y + w[i].z * v.z + w[i].w * v.w;
        }
        acc = wsum(acc);
        if (lane == 0) g_gates[job] = acc + ldg1(b_ih + job);
    }
    gbar(3);

    // ---- Phase E: redundant GRU elementwise -> s_vec = h_new ---------------
    __syncthreads();
    {
        const int i = t;
        const float gxr = g_gates[i],         ghr = g_gates[3 * H + i];
        const float gxz = g_gates[H + i],     ghz = g_gates[4 * H + i];
        const float gxn = g_gates[2 * H + i], ghn = g_gates[5 * H + i];
        const float r = 1.f / (1.f + expf(-(gxr + ghr)));
        const float z = 1.f / (1.f + expf(-(gxz + ghz)));
        const float n = tanhf(gxn + r * ghn);
        s_vec[i] = (1.f - z) * n + z * s_h0[i];
    }
    __syncthreads();

    // ---- Phase E2: big GEMV, warp-per-row; sticky prefix pinned in L2 ------
    for (int r = r0 + wid; r < r1; r += NW) {
        const float4* Wr = (const float4*)(out_W + (size_t)r * H);
        const float4* sv = (const float4*)s_vec;
        const uint64_t pol = (r - r0 < STICKY_ROWS) ? POL_L : POL_F;
        float4 w[8];
#pragma unroll
        for (int i = 0; i < 8; i++) w[i] = ldg4_pol(Wr + lane + i * 32, pol);
        float acc = 0.f;
#pragma unroll
        for (int i = 0; i < 8; i++) {
            float4 v = sv[lane + i * 32];
            acc += w[i].x * v.x + w[i].y * v.y + w[i].z * v.z + w[i].w * v.w;
        }
        acc = wsum(acc);
        if (lane == 0) s_logits[r - r0] = acc + s_outb[r - r0];
    }
    __syncthreads();

    // per-block LSE partial over own rows (smem-resident logits)
    {
        red[t]  = (t < nrows) ? s_logits[t] : NEG_SENT;
        red2[t] = (t < nrows) ? 1.f : 0.f;
        __syncthreads();
        for (int o = 512; o; o >>= 1) {
            if (t < o) {
                const float m2 = red[t + o], s2 = red2[t + o];
                const float nm = fmaxf(red[t], m2);
                red2[t] = red2[t] * expf(red[t] - nm) + s2 * expf(m2 - nm);
                red[t] = nm;
            }
            __syncthreads();
        }
        if (t == 0) { g_pm[b] = red[0]; g_ps[b] = red2[0]; }
    }
    gbar(4);

    // ---- Phase F: redundant combine of 148 partials (identical tree) -------
    {
        if (t < 256) {
            red[t]  = (t < GRID) ? g_pm[t] : NEG_SENT;
            red2[t] = (t < GRID) ? g_ps[t] : 0.f;
        }
        __syncthreads();
        for (int o = 128; o; o >>= 1) {
            if (t < o) {
                const float m2 = red[t + o], s2 = red2[t + o];
                const float nm = fmaxf(red[t], m2);
                red2[t] = red2[t] * expf(red[t] - nm) + s2 * expf(m2 - nm);
                red[t] = nm;
            }
            __syncthreads();
        }
        const float lse = red[0] + logf(red2[0]);
        if (t < nrows) out[r0 + t] = s_logits[t] - lse;
    }
}

extern "C" void kernel_launch(void* const* d_in, const int* in_sizes, int n_in,
                              void* d_out, int out_size) {
    const int*   x      = (const int*)  d_in[0];
    const float* enc    = (const float*)d_in[1];
    const float* hidden = (const float*)d_in[2];
    const float* emb    = (const float*)d_in[3];
    const float* attn_W = (const float*)d_in[4];
    const float* attn_b = (const float*)d_in[5];
    const float* comb_W = (const float*)d_in[6];
    const float* comb_b = (const float*)d_in[7];
    const float* W_ih   = (const float*)d_in[8];
    const float* W_hh   = (const float*)d_in[9];
    const float* b_ih   = (const float*)d_in[10];
    const float* b_hh   = (const float*)d_in[11];
    const float* out_W  = (const float*)d_in[12];
    const float* out_b  = (const float*)d_in[13];
    float* out = (float*)d_out;   // [0,V): logp ; [V,V+L): attn_weights

    k_reset<<<1, 32>>>();
    k_fused<<<GRID, TPB>>>(x, enc, hidden, emb, attn_W, attn_b, comb_W, comb_b,
                           W_ih, W_hh, b_ih, b_hh, out_W, out_b, out);
}